// round 8
// baseline (speedup 1.0000x reference)
#include <cuda_runtime.h>
#include <cuda_fp16.h>
#include <math.h>

#define NB 4
#define NN 15135
#define NE 302700
#define BN (NB * NN)
#define FIN0 8
#define NH 64
#define NFC 256
#define NEG_SLOPE 0.2f
#define CSR_BLOCKS 128

// ---------------------------------------------------------------------------
// Static device scratch (module-load zeroed; lin1/final restore entry state)
// ---------------------------------------------------------------------------
__device__ int     g_deg[NN];
__device__ int     g_cur[NN];
__device__ int     g_rowptr[NN + 1];
__device__ int     g_col[NE];
__device__ int     g_arrive;
__device__ int     g_flag;

__device__ __half2 g_hin_h[(size_t)NN * 128];   // [n][b*32 + f/2]
__device__ float   g_hout[3][BN * NH];          // [l][b][n][64]
__device__ float4  g_es4[NN];
__device__ float4  g_ed4[NN];
__device__ float4  g_w[NE];                     // overflow numerators (deg>32)
__device__ float   g_scores[BN];
__device__ float   g_h1[NB * NFC];

__device__ __forceinline__ float lrelu(float x) { return x >= 0.f ? x : NEG_SLOPE * x; }

// ---------------------------------------------------------------------------
// Fused CSR build: hist -> barrier -> scan(block 0) -> flag -> scatter
// ---------------------------------------------------------------------------
__global__ __launch_bounds__(1024) void csr_kernel(const int* __restrict__ ei) {
    int tid = threadIdx.x;
    int bid = blockIdx.x;

    for (int e = bid * 1024 + tid; e < NE; e += CSR_BLOCKS * 1024)
        atomicAdd(&g_deg[__ldg(ei + NE + e)], 1);
    __syncthreads();
    if (tid == 0) {
        __threadfence();
        atomicAdd(&g_arrive, 1);
    }

    if (bid == 0) {
        if (tid == 0) {
            while (*(volatile int*)&g_arrive != CSR_BLOCKS) __nanosleep(64);
            __threadfence();
        }
        __syncthreads();
        __shared__ int warpsums[32];
        __shared__ int carry;
        int lane = tid & 31, w = tid >> 5;
        if (tid == 0) { carry = 0; g_rowptr[0] = 0; }
        __syncthreads();
        for (int base = 0; base < NN; base += 4096) {
            int idx = base + tid * 4;
            int v0 = (idx     < NN) ? g_deg[idx]     : 0;
            int v1 = (idx + 1 < NN) ? g_deg[idx + 1] : 0;
            int v2 = (idx + 2 < NN) ? g_deg[idx + 2] : 0;
            int v3 = (idx + 3 < NN) ? g_deg[idx + 3] : 0;
            int s0 = v0, s1 = s0 + v1, s2 = s1 + v2, s3 = s2 + v3;
            int x = s3;
#pragma unroll
            for (int off = 1; off < 32; off <<= 1) {
                int y = __shfl_up_sync(0xffffffffu, x, off);
                if (lane >= off) x += y;
            }
            if (lane == 31) warpsums[w] = x;
            __syncthreads();
            if (tid < 32) {
                int s = warpsums[tid];
#pragma unroll
                for (int off = 1; off < 32; off <<= 1) {
                    int y = __shfl_up_sync(0xffffffffu, s, off);
                    if (tid >= off) s += y;
                }
                warpsums[tid] = s;
            }
            __syncthreads();
            int pre = x - s3 + (w > 0 ? warpsums[w - 1] : 0) + carry;
            if (idx     < NN) { g_cur[idx]     = pre;      g_rowptr[idx + 1] = pre + s0; }
            if (idx + 1 < NN) { g_cur[idx + 1] = pre + s0; g_rowptr[idx + 2] = pre + s1; }
            if (idx + 2 < NN) { g_cur[idx + 2] = pre + s1; g_rowptr[idx + 3] = pre + s2; }
            if (idx + 3 < NN) { g_cur[idx + 3] = pre + s2; g_rowptr[idx + 4] = pre + s3; }
            __syncthreads();
            if (tid == 0) carry += warpsums[31];
            __syncthreads();
        }
        __threadfence();
        __syncthreads();
        if (tid == 0) *(volatile int*)&g_flag = 1;
    } else {
        if (tid == 0) {
            while (*(volatile int*)&g_flag == 0) __nanosleep(64);
            __threadfence();
        }
        __syncthreads();
    }

    for (int e = bid * 1024 + tid; e < NE; e += CSR_BLOCKS * 1024) {
        int s = __ldg(ei + e);
        int d = __ldg(ei + NE + e);
        int pos = atomicAdd(&g_cur[d], 1);
        g_col[pos] = s;
    }
}

// ---------------------------------------------------------------------------
// Feature transform: register-tiled SGEMM.
// Block: 128 rows x 64 cols, 256 threads, thread = 4 rows x 8 cols.
// Xs transposed [f][row] (conflict-free), Ws [f][64].
// Emits fp16 gather table, fp32 hout, and es/ed.
// ---------------------------------------------------------------------------
template <int FIN>
__global__ __launch_bounds__(256) void transform_kernel(
        const float* __restrict__ x0, const float* __restrict__ W,
        const float* __restrict__ a_src, const float* __restrict__ a_dst,
        int layer) {
    __shared__ float Xs[FIN][128];
    __shared__ float Ws[FIN][NH];
    int t = threadIdx.x;

    for (int i = t; i < FIN * NH; i += 256) ((float*)Ws)[i] = W[i];

    int row0 = blockIdx.x * 128;
    const float* in = (layer == 0) ? x0 : g_hout[layer - 1];

    if (FIN == NH) {
        int r = t & 127;
        int fh = (t >> 7) * 32;
        int grow = row0 + r;
        const float* rp = in + (size_t)grow * NH + fh;
#pragma unroll
        for (int j = 0; j < 8; ++j) {
            float4 v = (grow < BN) ? *(const float4*)(rp + j * 4)
                                   : make_float4(0.f, 0.f, 0.f, 0.f);
            Xs[fh + j * 4 + 0][r] = v.x;
            Xs[fh + j * 4 + 1][r] = v.y;
            Xs[fh + j * 4 + 2][r] = v.z;
            Xs[fh + j * 4 + 3][r] = v.w;
        }
    } else {            // FIN == 8
        int r = t & 127;
        int fh = (t >> 7) * 4;
        int grow = row0 + r;
        float4 v = (grow < BN) ? *(const float4*)(in + (size_t)grow * 8 + fh)
                               : make_float4(0.f, 0.f, 0.f, 0.f);
        Xs[fh + 0][r] = v.x;
        Xs[fh + 1][r] = v.y;
        Xs[fh + 2][r] = v.z;
        Xs[fh + 3][r] = v.w;
    }
    __syncthreads();

    int rg = t >> 3;         // 0..31, 4 rows each
    int cg = t & 7;          // 0..7, 8 cols each
    int c0 = cg * 8;

    float acc[4][8];
#pragma unroll
    for (int i = 0; i < 4; ++i)
#pragma unroll
        for (int j = 0; j < 8; ++j) acc[i][j] = 0.f;

#pragma unroll 4
    for (int f = 0; f < FIN; ++f) {
        float4 xv = *(const float4*)&Xs[f][rg * 4];
        float4 wA = *(const float4*)&Ws[f][c0];
        float4 wB = *(const float4*)&Ws[f][c0 + 4];
        float xr[4] = {xv.x, xv.y, xv.z, xv.w};
        float wr[8] = {wA.x, wA.y, wA.z, wA.w, wB.x, wB.y, wB.z, wB.w};
#pragma unroll
        for (int i = 0; i < 4; ++i)
#pragma unroll
            for (int j = 0; j < 8; ++j)
                acc[i][j] = fmaf(xr[i], wr[j], acc[i][j]);
    }

    // attention vector slices for this thread's 8 cols
    float4 asA = *(const float4*)(a_src + c0);
    float4 asB = *(const float4*)(a_src + c0 + 4);
    float4 adA = *(const float4*)(a_dst + c0);
    float4 adB = *(const float4*)(a_dst + c0 + 4);
    float asr[8] = {asA.x, asA.y, asA.z, asA.w, asB.x, asB.y, asB.z, asB.w};
    float adr[8] = {adA.x, adA.y, adA.z, adA.w, adB.x, adB.y, adB.z, adB.w};

#pragma unroll
    for (int i = 0; i < 4; ++i) {
        int grow = row0 + rg * 4 + i;
        // es/ed partials, reduce over the 8 threads sharing this row
        float e_s = 0.f, e_d = 0.f;
#pragma unroll
        for (int j = 0; j < 8; ++j) {
            e_s = fmaf(acc[i][j], asr[j], e_s);
            e_d = fmaf(acc[i][j], adr[j], e_d);
        }
#pragma unroll
        for (int o = 4; o; o >>= 1) {
            e_s += __shfl_xor_sync(0xffffffffu, e_s, o);
            e_d += __shfl_xor_sync(0xffffffffu, e_d, o);
        }
        if (grow < BN) {
            int b = grow / NN;
            int n = grow - b * NN;
            // fp32 hout
            float4 oA = make_float4(acc[i][0], acc[i][1], acc[i][2], acc[i][3]);
            float4 oB = make_float4(acc[i][4], acc[i][5], acc[i][6], acc[i][7]);
            float* orow = g_hout[layer] + (size_t)grow * NH + c0;
            // NOTE: hout here stores PRE-aggregation transform... no wait —
            // hout[layer] is written by agg; transform writes only hin/es/ed.
            (void)orow; (void)oA; (void)oB;
            // fp16 gather table
            __half2 tmp[4];
            tmp[0] = __floats2half2_rn(acc[i][0], acc[i][1]);
            tmp[1] = __floats2half2_rn(acc[i][2], acc[i][3]);
            tmp[2] = __floats2half2_rn(acc[i][4], acc[i][5]);
            tmp[3] = __floats2half2_rn(acc[i][6], acc[i][7]);
            *(uint4*)(g_hin_h + (size_t)n * 128 + b * 32 + cg * 4) = *(uint4*)tmp;
            if (cg == 0) {
                ((float*)g_es4)[n * 4 + b] = e_s;
                ((float*)g_ed4)[n * 4 + b] = e_d;
            }
        }
    }
}

// ---------------------------------------------------------------------------
// GAT aggregation (unchanged from R6): two warps per node.
// ---------------------------------------------------------------------------
template <bool FUSE_SCORES>
__global__ __launch_bounds__(256) void agg_kernel(
        const float* __restrict__ bias, int layer,
        const float* __restrict__ fcw, const float* __restrict__ fcb) {
    __shared__ float2 s_w[8][32];
    __shared__ int    s_col[8][32];
    int wip = threadIdx.x >> 5;
    int lane = threadIdx.x & 31;
    int gwarp = blockIdx.x * 8 + wip;
    if (gwarp >= 2 * NN) return;
    int v = gwarp >> 1;
    int half = gwarp & 1;
    int r0 = g_rowptr[v];
    int r1 = g_rowptr[v + 1];
    int deg = r1 - r0;

    const float2* es2p = (const float2*)g_es4;
    float2 ed2 = ((const float2*)g_ed4)[2 * v + half];
    float2 es2 = es2p[2 * v + half];
    float2 vself = make_float2(lrelu(es2.x + ed2.x), lrelu(es2.y + ed2.y));

    bool have0 = (lane < deg);
    int s0 = have0 ? g_col[r0 + lane] : 0;
    if (have0) s_col[wip][lane] = s0;
    float2 e0 = es2p[2 * s0 + half];
    float2 v0 = make_float2(lrelu(e0.x + ed2.x), lrelu(e0.y + ed2.y));
    float2 mx = vself;
    if (have0) { mx.x = fmaxf(mx.x, v0.x); mx.y = fmaxf(mx.y, v0.y); }
    for (int i = r0 + lane + 32; i < r1; i += 32) {
        float2 e = es2p[2 * g_col[i] + half];
        mx.x = fmaxf(mx.x, lrelu(e.x + ed2.x));
        mx.y = fmaxf(mx.y, lrelu(e.y + ed2.y));
    }
#pragma unroll
    for (int o = 16; o; o >>= 1) {
        mx.x = fmaxf(mx.x, __shfl_xor_sync(0xffffffffu, mx.x, o));
        mx.y = fmaxf(mx.y, __shfl_xor_sync(0xffffffffu, mx.y, o));
    }

    float2 wself = make_float2(__expf(vself.x - mx.x), __expf(vself.y - mx.y));
    float2 ex0 = make_float2(__expf(v0.x - mx.x), __expf(v0.y - mx.y));
    float2 sm = make_float2(0.f, 0.f);
    if (have0) { s_w[wip][lane] = ex0; sm = ex0; }
    if (lane == 0) { sm.x += wself.x; sm.y += wself.y; }
    for (int i = r0 + lane + 32; i < r1; i += 32) {
        float2 e = es2p[2 * g_col[i] + half];
        float2 ex = make_float2(__expf(lrelu(e.x + ed2.x) - mx.x),
                                __expf(lrelu(e.y + ed2.y) - mx.y));
        ((float2*)&g_w[i])[half] = ex;
        sm.x += ex.x; sm.y += ex.y;
    }
#pragma unroll
    for (int o = 16; o; o >>= 1) {
        sm.x += __shfl_xor_sync(0xffffffffu, sm.x, o);
        sm.y += __shfl_xor_sync(0xffffffffu, sm.y, o);
    }
    bool loA = (lane < 16);
    float inv = 1.f / (loA ? sm.x : sm.y);
    __syncwarp();

    int bidx = 2 * half + (lane >> 4);
    int f0 = (lane & 15) * 4;
    int off2 = bidx * 32 + ((lane & 15) << 1);

    float4 acc = make_float4(0.f, 0.f, 0.f, 0.f);
    int kmax = deg < 32 ? deg : 32;
    for (int k = 0; k < kmax; ++k) {
        int s = s_col[wip][k];
        float2 w2 = s_w[wip][k];
        float wn = (loA ? w2.x : w2.y) * inv;
        uint2 rr = *(const uint2*)(g_hin_h + (size_t)s * 128 + off2);
        float2 a01 = __half22float2(*(__half2*)&rr.x);
        float2 a23 = __half22float2(*(__half2*)&rr.y);
        acc.x = fmaf(wn, a01.x, acc.x); acc.y = fmaf(wn, a01.y, acc.y);
        acc.z = fmaf(wn, a23.x, acc.z); acc.w = fmaf(wn, a23.y, acc.w);
    }
    for (int i = r0 + 32; i < r1; ++i) {
        int s = g_col[i];
        float2 w2 = ((const float2*)&g_w[i])[half];
        float wn = (loA ? w2.x : w2.y) * inv;
        uint2 rr = *(const uint2*)(g_hin_h + (size_t)s * 128 + off2);
        float2 a01 = __half22float2(*(__half2*)&rr.x);
        float2 a23 = __half22float2(*(__half2*)&rr.y);
        acc.x = fmaf(wn, a01.x, acc.x); acc.y = fmaf(wn, a01.y, acc.y);
        acc.z = fmaf(wn, a23.x, acc.z); acc.w = fmaf(wn, a23.y, acc.w);
    }
    {
        float wn = (loA ? wself.x : wself.y) * inv;
        uint2 rr = *(const uint2*)(g_hin_h + (size_t)v * 128 + off2);
        float2 a01 = __half22float2(*(__half2*)&rr.x);
        float2 a23 = __half22float2(*(__half2*)&rr.y);
        acc.x = fmaf(wn, a01.x, acc.x); acc.y = fmaf(wn, a01.y, acc.y);
        acc.z = fmaf(wn, a23.x, acc.z); acc.w = fmaf(wn, a23.y, acc.w);
    }

    float4 b4 = *(const float4*)(bias + f0);
    float4 o4;
    o4.x = fmaxf(acc.x + b4.x, 0.f); o4.y = fmaxf(acc.y + b4.y, 0.f);
    o4.z = fmaxf(acc.z + b4.z, 0.f); o4.w = fmaxf(acc.w + b4.w, 0.f);
    *(float4*)(g_hout[layer] + ((size_t)(bidx * NN + v)) * NH + f0) = o4;

    if (FUSE_SCORES) {
        float4 w0 = make_float4(fcw[(f0 + 0) * 3 + 0], fcw[(f0 + 1) * 3 + 0],
                                fcw[(f0 + 2) * 3 + 0], fcw[(f0 + 3) * 3 + 0]);
        float4 w1 = make_float4(fcw[(f0 + 0) * 3 + 1], fcw[(f0 + 1) * 3 + 1],
                                fcw[(f0 + 2) * 3 + 1], fcw[(f0 + 3) * 3 + 1]);
        float4 w2 = make_float4(fcw[(f0 + 0) * 3 + 2], fcw[(f0 + 1) * 3 + 2],
                                fcw[(f0 + 2) * 3 + 2], fcw[(f0 + 3) * 3 + 2]);
        float4 h0 = *(const float4*)(g_hout[0] + ((size_t)(bidx * NN + v)) * NH + f0);
        float4 h1 = *(const float4*)(g_hout[1] + ((size_t)(bidx * NN + v)) * NH + f0);
        float p = o4.x * w2.x + o4.y * w2.y + o4.z * w2.z + o4.w * w2.w
                + h0.x * w0.x + h0.y * w0.y + h0.z * w0.z + h0.w * w0.w
                + h1.x * w1.x + h1.y * w1.y + h1.z * w1.z + h1.w * w1.w;
#pragma unroll
        for (int o = 8; o; o >>= 1) p += __shfl_xor_sync(0xffffffffu, p, o);
        if ((lane & 15) == 0) g_scores[bidx * NN + v] = p + fcb[0];
    }
}

// ---------------------------------------------------------------------------
__global__ void lin1_kernel(const float* __restrict__ w) {
    int f = threadIdx.x;
    int chunk = (NN + gridDim.x - 1) / gridDim.x;
    int n0 = blockIdx.x * chunk;
    int n1 = n0 + chunk;
    if (n1 > NN) n1 = NN;

    for (int i = n0 + f; i < n1; i += blockDim.x) g_deg[i] = 0;
    if (blockIdx.x == 0 && f == 0) { g_arrive = 0; g_flag = 0; }

    float acc[NB] = {0.f, 0.f, 0.f, 0.f};
    for (int n = n0; n < n1; ++n) {
        float wv = w[(size_t)n * NFC + f];
#pragma unroll
        for (int b = 0; b < NB; ++b)
            acc[b] = fmaf(g_scores[b * NN + n], wv, acc[b]);
    }
#pragma unroll
    for (int b = 0; b < NB; ++b)
        atomicAdd(&g_h1[b * NFC + f], acc[b]);
}

__global__ void final_kernel(const float* __restrict__ l1b,
                             const float* __restrict__ l2w,
                             const float* __restrict__ l2b,
                             float* __restrict__ out) {
    __shared__ float s0[NFC], s1[NFC];
    int f = threadIdx.x;
    for (int b = 0; b < NB; ++b) {
        float hv = fmaxf(g_h1[b * NFC + f] + l1b[f], 0.f);
        g_h1[b * NFC + f] = 0.f;
        s0[f] = hv * l2w[f * 2 + 0];
        s1[f] = hv * l2w[f * 2 + 1];
        __syncthreads();
        for (int off = 128; off; off >>= 1) {
            if (f < off) { s0[f] += s0[f + off]; s1[f] += s1[f + off]; }
            __syncthreads();
        }
        if (f == 0) {
            float l0 = s0[0] + l2b[0];
            float l1 = s1[0] + l2b[1];
            float m = fmaxf(l0, l1);
            float lse = m + logf(expf(l0 - m) + expf(l1 - m));
            out[b * 2 + 0] = l0 - lse;
            out[b * 2 + 1] = l1 - lse;
        }
        __syncthreads();
    }
}

// ---------------------------------------------------------------------------
extern "C" void kernel_launch(void* const* d_in, const int* in_sizes, int n_in,
                              void* d_out, int out_size) {
    const float* x      = (const float*)d_in[0];
    const int*   ei     = (const int*)d_in[1];
    const float* W[3]   = {(const float*)d_in[3], (const float*)d_in[7],  (const float*)d_in[11]};
    const float* as_[3] = {(const float*)d_in[4], (const float*)d_in[8],  (const float*)d_in[12]};
    const float* ad_[3] = {(const float*)d_in[5], (const float*)d_in[9],  (const float*)d_in[13]};
    const float* bb[3]  = {(const float*)d_in[6], (const float*)d_in[10], (const float*)d_in[14]};
    const float* fcw    = (const float*)d_in[15];
    const float* fcb    = (const float*)d_in[16];
    const float* l1w    = (const float*)d_in[17];
    const float* l1b    = (const float*)d_in[18];
    const float* l2w    = (const float*)d_in[19];
    const float* l2b    = (const float*)d_in[20];
    float* out = (float*)d_out;

    csr_kernel<<<CSR_BLOCKS, 1024>>>(ei);

    int gridT = (BN + 127) / 128;
    int gridA = (2 * NN + 7) / 8;

    transform_kernel<FIN0><<<gridT, 256>>>(x, W[0], as_[0], ad_[0], 0);
    agg_kernel<false><<<gridA, 256>>>(bb[0], 0, fcw, fcb);
    transform_kernel<NH><<<gridT, 256>>>(x, W[1], as_[1], ad_[1], 1);
    agg_kernel<false><<<gridA, 256>>>(bb[1], 1, fcw, fcb);
    transform_kernel<NH><<<gridT, 256>>>(x, W[2], as_[2], ad_[2], 2);
    agg_kernel<true><<<gridA, 256>>>(bb[2], 2, fcw, fcb);

    lin1_kernel<<<128, 256>>>(l1w);
    final_kernel<<<1, 256>>>(l1b, l2w, l2b, out);
}

// round 9
// speedup vs baseline: 1.0075x; 1.0075x over previous
#include <cuda_runtime.h>
#include <cuda_fp16.h>
#include <math.h>

#define NB 4
#define NN 15135
#define NE 302700
#define BN (NB * NN)
#define FIN0 8
#define NH 64
#define NFC 256
#define NEG_SLOPE 0.2f
#define CSR_BLOCKS 128

// ---------------------------------------------------------------------------
// Static device scratch (module-load zeroed; lin1/final restore entry state)
// ---------------------------------------------------------------------------
__device__ int     g_deg[NN];
__device__ int     g_cur[NN];
__device__ int     g_rowptr[NN + 1];
__device__ int     g_col[NE];
__device__ int     g_arrive;
__device__ int     g_flag;

__device__ __half2 g_hin_h[(size_t)NN * 128];   // [n][b*32 + f/2]
__device__ float   g_hout[3][BN * NH];          // [l][b][n][64]
__device__ float4  g_es4[NN];
__device__ float4  g_ed4[NN];
__device__ float4  g_w[NE];                     // overflow numerators (deg>32)
__device__ float   g_scores[BN];
__device__ float   g_h1[NB * NFC];

__device__ __forceinline__ float lrelu(float x) { return x >= 0.f ? x : NEG_SLOPE * x; }

// ---------------------------------------------------------------------------
// Fused CSR build: hist -> barrier -> scan(block 0) -> flag -> scatter
// ---------------------------------------------------------------------------
__global__ __launch_bounds__(1024) void csr_kernel(const int* __restrict__ ei) {
    int tid = threadIdx.x;
    int bid = blockIdx.x;

    for (int e = bid * 1024 + tid; e < NE; e += CSR_BLOCKS * 1024)
        atomicAdd(&g_deg[__ldg(ei + NE + e)], 1);
    __syncthreads();
    if (tid == 0) {
        __threadfence();
        atomicAdd(&g_arrive, 1);
    }

    if (bid == 0) {
        if (tid == 0) {
            while (*(volatile int*)&g_arrive != CSR_BLOCKS) __nanosleep(64);
            __threadfence();
        }
        __syncthreads();
        __shared__ int warpsums[32];
        __shared__ int carry;
        int lane = tid & 31, w = tid >> 5;
        if (tid == 0) { carry = 0; g_rowptr[0] = 0; }
        __syncthreads();
        for (int base = 0; base < NN; base += 4096) {
            int idx = base + tid * 4;
            int v0 = (idx     < NN) ? g_deg[idx]     : 0;
            int v1 = (idx + 1 < NN) ? g_deg[idx + 1] : 0;
            int v2 = (idx + 2 < NN) ? g_deg[idx + 2] : 0;
            int v3 = (idx + 3 < NN) ? g_deg[idx + 3] : 0;
            int s0 = v0, s1 = s0 + v1, s2 = s1 + v2, s3 = s2 + v3;
            int x = s3;
#pragma unroll
            for (int off = 1; off < 32; off <<= 1) {
                int y = __shfl_up_sync(0xffffffffu, x, off);
                if (lane >= off) x += y;
            }
            if (lane == 31) warpsums[w] = x;
            __syncthreads();
            if (tid < 32) {
                int s = warpsums[tid];
#pragma unroll
                for (int off = 1; off < 32; off <<= 1) {
                    int y = __shfl_up_sync(0xffffffffu, s, off);
                    if (tid >= off) s += y;
                }
                warpsums[tid] = s;
            }
            __syncthreads();
            int pre = x - s3 + (w > 0 ? warpsums[w - 1] : 0) + carry;
            if (idx     < NN) { g_cur[idx]     = pre;      g_rowptr[idx + 1] = pre + s0; }
            if (idx + 1 < NN) { g_cur[idx + 1] = pre + s0; g_rowptr[idx + 2] = pre + s1; }
            if (idx + 2 < NN) { g_cur[idx + 2] = pre + s1; g_rowptr[idx + 3] = pre + s2; }
            if (idx + 3 < NN) { g_cur[idx + 3] = pre + s2; g_rowptr[idx + 4] = pre + s3; }
            __syncthreads();
            if (tid == 0) carry += warpsums[31];
            __syncthreads();
        }
        __threadfence();
        __syncthreads();
        if (tid == 0) *(volatile int*)&g_flag = 1;
    } else {
        if (tid == 0) {
            while (*(volatile int*)&g_flag == 0) __nanosleep(64);
            __threadfence();
        }
        __syncthreads();
    }

    for (int e = bid * 1024 + tid; e < NE; e += CSR_BLOCKS * 1024) {
        int s = __ldg(ei + e);
        int d = __ldg(ei + NE + e);
        int pos = atomicAdd(&g_cur[d], 1);
        g_col[pos] = s;
    }
}

// ---------------------------------------------------------------------------
// Feature transform: register-tiled SGEMM.
// Block: 128 rows x 64 cols, 256 threads, thread = 4 rows x 8 cols.
// Xs transposed [f][row] (conflict-free), Ws [f][64].
// Emits fp16 gather table, fp32 hout, and es/ed.
// ---------------------------------------------------------------------------
template <int FIN>
__global__ __launch_bounds__(256) void transform_kernel(
        const float* __restrict__ x0, const float* __restrict__ W,
        const float* __restrict__ a_src, const float* __restrict__ a_dst,
        int layer) {
    __shared__ float Xs[FIN][128];
    __shared__ float Ws[FIN][NH];
    int t = threadIdx.x;

    for (int i = t; i < FIN * NH; i += 256) ((float*)Ws)[i] = W[i];

    int row0 = blockIdx.x * 128;
    const float* in = (layer == 0) ? x0 : g_hout[layer - 1];

    if (FIN == NH) {
        int r = t & 127;
        int fh = (t >> 7) * 32;
        int grow = row0 + r;
        const float* rp = in + (size_t)grow * NH + fh;
#pragma unroll
        for (int j = 0; j < 8; ++j) {
            float4 v = (grow < BN) ? *(const float4*)(rp + j * 4)
                                   : make_float4(0.f, 0.f, 0.f, 0.f);
            Xs[fh + j * 4 + 0][r] = v.x;
            Xs[fh + j * 4 + 1][r] = v.y;
            Xs[fh + j * 4 + 2][r] = v.z;
            Xs[fh + j * 4 + 3][r] = v.w;
        }
    } else {            // FIN == 8
        int r = t & 127;
        int fh = (t >> 7) * 4;
        int grow = row0 + r;
        float4 v = (grow < BN) ? *(const float4*)(in + (size_t)grow * 8 + fh)
                               : make_float4(0.f, 0.f, 0.f, 0.f);
        Xs[fh + 0][r] = v.x;
        Xs[fh + 1][r] = v.y;
        Xs[fh + 2][r] = v.z;
        Xs[fh + 3][r] = v.w;
    }
    __syncthreads();

    int rg = t >> 3;         // 0..31, 4 rows each
    int cg = t & 7;          // 0..7, 8 cols each
    int c0 = cg * 8;

    float acc[4][8];
#pragma unroll
    for (int i = 0; i < 4; ++i)
#pragma unroll
        for (int j = 0; j < 8; ++j) acc[i][j] = 0.f;

#pragma unroll 4
    for (int f = 0; f < FIN; ++f) {
        float4 xv = *(const float4*)&Xs[f][rg * 4];
        float4 wA = *(const float4*)&Ws[f][c0];
        float4 wB = *(const float4*)&Ws[f][c0 + 4];
        float xr[4] = {xv.x, xv.y, xv.z, xv.w};
        float wr[8] = {wA.x, wA.y, wA.z, wA.w, wB.x, wB.y, wB.z, wB.w};
#pragma unroll
        for (int i = 0; i < 4; ++i)
#pragma unroll
            for (int j = 0; j < 8; ++j)
                acc[i][j] = fmaf(xr[i], wr[j], acc[i][j]);
    }

    // attention vector slices for this thread's 8 cols
    float4 asA = *(const float4*)(a_src + c0);
    float4 asB = *(const float4*)(a_src + c0 + 4);
    float4 adA = *(const float4*)(a_dst + c0);
    float4 adB = *(const float4*)(a_dst + c0 + 4);
    float asr[8] = {asA.x, asA.y, asA.z, asA.w, asB.x, asB.y, asB.z, asB.w};
    float adr[8] = {adA.x, adA.y, adA.z, adA.w, adB.x, adB.y, adB.z, adB.w};

#pragma unroll
    for (int i = 0; i < 4; ++i) {
        int grow = row0 + rg * 4 + i;
        // es/ed partials, reduce over the 8 threads sharing this row
        float e_s = 0.f, e_d = 0.f;
#pragma unroll
        for (int j = 0; j < 8; ++j) {
            e_s = fmaf(acc[i][j], asr[j], e_s);
            e_d = fmaf(acc[i][j], adr[j], e_d);
        }
#pragma unroll
        for (int o = 4; o; o >>= 1) {
            e_s += __shfl_xor_sync(0xffffffffu, e_s, o);
            e_d += __shfl_xor_sync(0xffffffffu, e_d, o);
        }
        if (grow < BN) {
            int b = grow / NN;
            int n = grow - b * NN;
            // fp32 hout
            float4 oA = make_float4(acc[i][0], acc[i][1], acc[i][2], acc[i][3]);
            float4 oB = make_float4(acc[i][4], acc[i][5], acc[i][6], acc[i][7]);
            float* orow = g_hout[layer] + (size_t)grow * NH + c0;
            // NOTE: hout here stores PRE-aggregation transform... no wait —
            // hout[layer] is written by agg; transform writes only hin/es/ed.
            (void)orow; (void)oA; (void)oB;
            // fp16 gather table
            __half2 tmp[4];
            tmp[0] = __floats2half2_rn(acc[i][0], acc[i][1]);
            tmp[1] = __floats2half2_rn(acc[i][2], acc[i][3]);
            tmp[2] = __floats2half2_rn(acc[i][4], acc[i][5]);
            tmp[3] = __floats2half2_rn(acc[i][6], acc[i][7]);
            *(uint4*)(g_hin_h + (size_t)n * 128 + b * 32 + cg * 4) = *(uint4*)tmp;
            if (cg == 0) {
                ((float*)g_es4)[n * 4 + b] = e_s;
                ((float*)g_ed4)[n * 4 + b] = e_d;
            }
        }
    }
}

// ---------------------------------------------------------------------------
// GAT aggregation (unchanged from R6): two warps per node.
// ---------------------------------------------------------------------------
template <bool FUSE_SCORES>
__global__ __launch_bounds__(256) void agg_kernel(
        const float* __restrict__ bias, int layer,
        const float* __restrict__ fcw, const float* __restrict__ fcb) {
    __shared__ float2 s_w[8][32];
    __shared__ int    s_col[8][32];
    int wip = threadIdx.x >> 5;
    int lane = threadIdx.x & 31;
    int gwarp = blockIdx.x * 8 + wip;
    if (gwarp >= 2 * NN) return;
    int v = gwarp >> 1;
    int half = gwarp & 1;
    int r0 = g_rowptr[v];
    int r1 = g_rowptr[v + 1];
    int deg = r1 - r0;

    const float2* es2p = (const float2*)g_es4;
    float2 ed2 = ((const float2*)g_ed4)[2 * v + half];
    float2 es2 = es2p[2 * v + half];
    float2 vself = make_float2(lrelu(es2.x + ed2.x), lrelu(es2.y + ed2.y));

    bool have0 = (lane < deg);
    int s0 = have0 ? g_col[r0 + lane] : 0;
    if (have0) s_col[wip][lane] = s0;
    float2 e0 = es2p[2 * s0 + half];
    float2 v0 = make_float2(lrelu(e0.x + ed2.x), lrelu(e0.y + ed2.y));
    float2 mx = vself;
    if (have0) { mx.x = fmaxf(mx.x, v0.x); mx.y = fmaxf(mx.y, v0.y); }
    for (int i = r0 + lane + 32; i < r1; i += 32) {
        float2 e = es2p[2 * g_col[i] + half];
        mx.x = fmaxf(mx.x, lrelu(e.x + ed2.x));
        mx.y = fmaxf(mx.y, lrelu(e.y + ed2.y));
    }
#pragma unroll
    for (int o = 16; o; o >>= 1) {
        mx.x = fmaxf(mx.x, __shfl_xor_sync(0xffffffffu, mx.x, o));
        mx.y = fmaxf(mx.y, __shfl_xor_sync(0xffffffffu, mx.y, o));
    }

    float2 wself = make_float2(__expf(vself.x - mx.x), __expf(vself.y - mx.y));
    float2 ex0 = make_float2(__expf(v0.x - mx.x), __expf(v0.y - mx.y));
    float2 sm = make_float2(0.f, 0.f);
    if (have0) { s_w[wip][lane] = ex0; sm = ex0; }
    if (lane == 0) { sm.x += wself.x; sm.y += wself.y; }
    for (int i = r0 + lane + 32; i < r1; i += 32) {
        float2 e = es2p[2 * g_col[i] + half];
        float2 ex = make_float2(__expf(lrelu(e.x + ed2.x) - mx.x),
                                __expf(lrelu(e.y + ed2.y) - mx.y));
        ((float2*)&g_w[i])[half] = ex;
        sm.x += ex.x; sm.y += ex.y;
    }
#pragma unroll
    for (int o = 16; o; o >>= 1) {
        sm.x += __shfl_xor_sync(0xffffffffu, sm.x, o);
        sm.y += __shfl_xor_sync(0xffffffffu, sm.y, o);
    }
    bool loA = (lane < 16);
    float inv = 1.f / (loA ? sm.x : sm.y);
    __syncwarp();

    int bidx = 2 * half + (lane >> 4);
    int f0 = (lane & 15) * 4;
    int off2 = bidx * 32 + ((lane & 15) << 1);

    float4 acc = make_float4(0.f, 0.f, 0.f, 0.f);
    int kmax = deg < 32 ? deg : 32;
    for (int k = 0; k < kmax; ++k) {
        int s = s_col[wip][k];
        float2 w2 = s_w[wip][k];
        float wn = (loA ? w2.x : w2.y) * inv;
        uint2 rr = *(const uint2*)(g_hin_h + (size_t)s * 128 + off2);
        float2 a01 = __half22float2(*(__half2*)&rr.x);
        float2 a23 = __half22float2(*(__half2*)&rr.y);
        acc.x = fmaf(wn, a01.x, acc.x); acc.y = fmaf(wn, a01.y, acc.y);
        acc.z = fmaf(wn, a23.x, acc.z); acc.w = fmaf(wn, a23.y, acc.w);
    }
    for (int i = r0 + 32; i < r1; ++i) {
        int s = g_col[i];
        float2 w2 = ((const float2*)&g_w[i])[half];
        float wn = (loA ? w2.x : w2.y) * inv;
        uint2 rr = *(const uint2*)(g_hin_h + (size_t)s * 128 + off2);
        float2 a01 = __half22float2(*(__half2*)&rr.x);
        float2 a23 = __half22float2(*(__half2*)&rr.y);
        acc.x = fmaf(wn, a01.x, acc.x); acc.y = fmaf(wn, a01.y, acc.y);
        acc.z = fmaf(wn, a23.x, acc.z); acc.w = fmaf(wn, a23.y, acc.w);
    }
    {
        float wn = (loA ? wself.x : wself.y) * inv;
        uint2 rr = *(const uint2*)(g_hin_h + (size_t)v * 128 + off2);
        float2 a01 = __half22float2(*(__half2*)&rr.x);
        float2 a23 = __half22float2(*(__half2*)&rr.y);
        acc.x = fmaf(wn, a01.x, acc.x); acc.y = fmaf(wn, a01.y, acc.y);
        acc.z = fmaf(wn, a23.x, acc.z); acc.w = fmaf(wn, a23.y, acc.w);
    }

    float4 b4 = *(const float4*)(bias + f0);
    float4 o4;
    o4.x = fmaxf(acc.x + b4.x, 0.f); o4.y = fmaxf(acc.y + b4.y, 0.f);
    o4.z = fmaxf(acc.z + b4.z, 0.f); o4.w = fmaxf(acc.w + b4.w, 0.f);
    *(float4*)(g_hout[layer] + ((size_t)(bidx * NN + v)) * NH + f0) = o4;

    if (FUSE_SCORES) {
        float4 w0 = make_float4(fcw[(f0 + 0) * 3 + 0], fcw[(f0 + 1) * 3 + 0],
                                fcw[(f0 + 2) * 3 + 0], fcw[(f0 + 3) * 3 + 0]);
        float4 w1 = make_float4(fcw[(f0 + 0) * 3 + 1], fcw[(f0 + 1) * 3 + 1],
                                fcw[(f0 + 2) * 3 + 1], fcw[(f0 + 3) * 3 + 1]);
        float4 w2 = make_float4(fcw[(f0 + 0) * 3 + 2], fcw[(f0 + 1) * 3 + 2],
                                fcw[(f0 + 2) * 3 + 2], fcw[(f0 + 3) * 3 + 2]);
        float4 h0 = *(const float4*)(g_hout[0] + ((size_t)(bidx * NN + v)) * NH + f0);
        float4 h1 = *(const float4*)(g_hout[1] + ((size_t)(bidx * NN + v)) * NH + f0);
        float p = o4.x * w2.x + o4.y * w2.y + o4.z * w2.z + o4.w * w2.w
                + h0.x * w0.x + h0.y * w0.y + h0.z * w0.z + h0.w * w0.w
                + h1.x * w1.x + h1.y * w1.y + h1.z * w1.z + h1.w * w1.w;
#pragma unroll
        for (int o = 8; o; o >>= 1) p += __shfl_xor_sync(0xffffffffu, p, o);
        if ((lane & 15) == 0) g_scores[bidx * NN + v] = p + fcb[0];
    }
}

// ---------------------------------------------------------------------------
__global__ void lin1_kernel(const float* __restrict__ w) {
    int f = threadIdx.x;
    int chunk = (NN + gridDim.x - 1) / gridDim.x;
    int n0 = blockIdx.x * chunk;
    int n1 = n0 + chunk;
    if (n1 > NN) n1 = NN;

    for (int i = n0 + f; i < n1; i += blockDim.x) g_deg[i] = 0;
    if (blockIdx.x == 0 && f == 0) { g_arrive = 0; g_flag = 0; }

    float acc[NB] = {0.f, 0.f, 0.f, 0.f};
    for (int n = n0; n < n1; ++n) {
        float wv = w[(size_t)n * NFC + f];
#pragma unroll
        for (int b = 0; b < NB; ++b)
            acc[b] = fmaf(g_scores[b * NN + n], wv, acc[b]);
    }
#pragma unroll
    for (int b = 0; b < NB; ++b)
        atomicAdd(&g_h1[b * NFC + f], acc[b]);
}

__global__ void final_kernel(const float* __restrict__ l1b,
                             const float* __restrict__ l2w,
                             const float* __restrict__ l2b,
                             float* __restrict__ out) {
    __shared__ float s0[NFC], s1[NFC];
    int f = threadIdx.x;
    for (int b = 0; b < NB; ++b) {
        float hv = fmaxf(g_h1[b * NFC + f] + l1b[f], 0.f);
        g_h1[b * NFC + f] = 0.f;
        s0[f] = hv * l2w[f * 2 + 0];
        s1[f] = hv * l2w[f * 2 + 1];
        __syncthreads();
        for (int off = 128; off; off >>= 1) {
            if (f < off) { s0[f] += s0[f + off]; s1[f] += s1[f + off]; }
            __syncthreads();
        }
        if (f == 0) {
            float l0 = s0[0] + l2b[0];
            float l1 = s1[0] + l2b[1];
            float m = fmaxf(l0, l1);
            float lse = m + logf(expf(l0 - m) + expf(l1 - m));
            out[b * 2 + 0] = l0 - lse;
            out[b * 2 + 1] = l1 - lse;
        }
        __syncthreads();
    }
}

// ---------------------------------------------------------------------------
extern "C" void kernel_launch(void* const* d_in, const int* in_sizes, int n_in,
                              void* d_out, int out_size) {
    const float* x      = (const float*)d_in[0];
    const int*   ei     = (const int*)d_in[1];
    const float* W[3]   = {(const float*)d_in[3], (const float*)d_in[7],  (const float*)d_in[11]};
    const float* as_[3] = {(const float*)d_in[4], (const float*)d_in[8],  (const float*)d_in[12]};
    const float* ad_[3] = {(const float*)d_in[5], (const float*)d_in[9],  (const float*)d_in[13]};
    const float* bb[3]  = {(const float*)d_in[6], (const float*)d_in[10], (const float*)d_in[14]};
    const float* fcw    = (const float*)d_in[15];
    const float* fcb    = (const float*)d_in[16];
    const float* l1w    = (const float*)d_in[17];
    const float* l1b    = (const float*)d_in[18];
    const float* l2w    = (const float*)d_in[19];
    const float* l2b    = (const float*)d_in[20];
    float* out = (float*)d_out;

    csr_kernel<<<CSR_BLOCKS, 1024>>>(ei);

    int gridT = (BN + 127) / 128;
    int gridA = (2 * NN + 7) / 8;

    transform_kernel<FIN0><<<gridT, 256>>>(x, W[0], as_[0], ad_[0], 0);
    agg_kernel<false><<<gridA, 256>>>(bb[0], 0, fcw, fcb);
    transform_kernel<NH><<<gridT, 256>>>(x, W[1], as_[1], ad_[1], 1);
    agg_kernel<false><<<gridA, 256>>>(bb[1], 1, fcw, fcb);
    transform_kernel<NH><<<gridT, 256>>>(x, W[2], as_[2], ad_[2], 2);
    agg_kernel<true><<<gridA, 256>>>(bb[2], 2, fcw, fcb);

    lin1_kernel<<<128, 256>>>(l1w);
    final_kernel<<<1, 256>>>(l1b, l2w, l2b, out);
}